// round 17
// baseline (speedup 1.0000x reference)
#include <cuda_runtime.h>
#include <cuda_bf16.h>
#include <cstdint>

// Problem constants
#define BATCH 4
#define SEQ   1024
#define HID   2048
#define NHEAD 16
#define NKV   2
#define HD    128
#define TOK   (BATCH*SEQ)          // 4096
#define KVDIM (NKV*HD)             // 256
#define OUT_ELEMS ((size_t)TOK*HID)
#define BUF_ELEMS ((size_t)2*TOK*2*NKV*HD)

// Scratch (device globals — no allocation allowed)
__device__ float g_K[TOK*KVDIM];
__device__ float g_V[TOK*KVDIM];
// pre-split (packed bf16 hi|lo) operands, flat format:
// per row, per 16-float k-group: [hi p0..p7][lo p0..p7] (16 u32)
__device__ uint32_t g_xs[TOK*HID];
__device__ uint32_t g_qws[HID*HID];
__device__ uint32_t g_kws[KVDIM*HID];
__device__ uint32_t g_vws[KVDIM*HID];
__device__ uint32_t g_ows[HID*HID];
__device__ uint32_t g_As[TOK*HID];      // attention output, written pre-split
// pre-split attention operands
__device__ uint32_t g_Qs[TOK*HID];
__device__ uint32_t g_Ks[TOK*KVDIM];
__device__ uint32_t g_Vt[(size_t)BATCH*NKV*HD*SEQ];

// ---------------------------------------------------------------------------
// bf16 split helpers
// ---------------------------------------------------------------------------
__device__ __forceinline__ void split_bf16(float x0, float x1,
                                           uint32_t& hi, uint32_t& lo)
{
    asm("cvt.rn.bf16x2.f32 %0, %1, %2;" : "=r"(hi) : "f"(x1), "f"(x0));
    float h0 = __uint_as_float(hi << 16);
    float h1 = __uint_as_float(hi & 0xffff0000u);
    asm("cvt.rn.bf16x2.f32 %0, %1, %2;" : "=r"(lo) : "f"(x1 - h1), "f"(x0 - h0));
}

__device__ __forceinline__ void mma_bf16(float c[4],
    uint32_t a0, uint32_t a1, uint32_t a2, uint32_t a3,
    uint32_t b0, uint32_t b1)
{
    asm volatile(
        "mma.sync.aligned.m16n8k16.row.col.f32.bf16.bf16.f32 "
        "{%0,%1,%2,%3}, {%4,%5,%6,%7}, {%8,%9}, {%0,%1,%2,%3};"
        : "+f"(c[0]), "+f"(c[1]), "+f"(c[2]), "+f"(c[3])
        : "r"(a0), "r"(a1), "r"(a2), "r"(a3), "r"(b0), "r"(b1));
}

__device__ __forceinline__ void cpa16(uint32_t smem_addr, const void* gptr) {
    asm volatile("cp.async.ca.shared.global [%0], [%1], 16;\n"
                 :: "r"(smem_addr), "l"(gptr));
}

// ---------------------------------------------------------------------------
// Pre-split kernel: fp32 -> packed hi/lo flat layout.
// ---------------------------------------------------------------------------
__global__ void presplit_kernel(const float* __restrict__ src,
                                uint32_t* __restrict__ dst, int n8)
{
    int idx = blockIdx.x * blockDim.x + threadIdx.x;
    if (idx >= n8) return;
    const float4 v0 = *(const float4*)(src + (size_t)idx*8);
    const float4 v1 = *(const float4*)(src + (size_t)idx*8 + 4);
    uint4 h, l;
    split_bf16(v0.x, v0.y, h.x, l.x);
    split_bf16(v0.z, v0.w, h.y, l.y);
    split_bf16(v1.x, v1.y, h.z, l.z);
    split_bf16(v1.z, v1.w, h.w, l.w);
    size_t base = (size_t)(idx >> 1)*16 + (idx & 1)*4;
    *(uint4*)(dst + base)     = h;
    *(uint4*)(dst + base + 8) = l;
}

// ---------------------------------------------------------------------------
// GEMM-NT on pre-split operands, KT=32, 2-stage cp.async, 2 CTAs/SM.
// Up to 3 output sets via blockIdx.x thresholds.
// fuse=1 (QKV): set0=Q -> rope+split -> Qs only;
//               set1=K -> rope+split -> Ks + roped fp32 K;
//               set2=V -> fp32 V + transpose+split -> Vt.
// fuse=0: plain fp32 epilogue (O-proj).
// Epilogue exchange tile CT reuses pipeline smem (stride 130, float2-aligned).
// ---------------------------------------------------------------------------
#define GST2 40
#define NK2 (HID/32)
#define GEMM_SMEM (2*2*128*GST2*4)   // 81920 bytes
#define CTS 130                      // 128*130*4 = 66560 <= 81920

__global__ __launch_bounds__(256, 2) void gemm_big_kernel(
    const uint32_t* __restrict__ A,
    const uint32_t* __restrict__ B0, const float* __restrict__ bias0,
    float* __restrict__ C0, int N0,
    const uint32_t* __restrict__ B1, const float* __restrict__ bias1,
    float* __restrict__ C1, int N1,
    const uint32_t* __restrict__ B2, const float* __restrict__ bias2,
    float* __restrict__ C2, int N2,
    int s1, int s2, int fuse,
    const float* __restrict__ cosb, const float* __restrict__ sinb,
    uint32_t* __restrict__ Qs, uint32_t* __restrict__ Ks,
    uint32_t* __restrict__ Vt)
{
    extern __shared__ __align__(16) uint32_t dyn[];
    uint32_t* Asm = dyn;
    uint32_t* Bsm = dyn + 2*128*GST2;

    const int bx = blockIdx.x;
    const int set = (bx >= s1) + (bx >= s2);
    const uint32_t* B = set == 0 ? B0 : (set == 1 ? B1 : B2);
    const float* bias = set == 0 ? bias0 : (set == 1 ? bias1 : bias2);
    float* C          = set == 0 ? C0 : (set == 1 ? C1 : C2);
    const int N       = set == 0 ? N0 : (set == 1 ? N1 : N2);
    const int n0      = (bx - (set == 0 ? 0 : (set == 1 ? s1 : s2))) * 128;

    const int tid  = threadIdx.x;
    const int lane = tid & 31;
    const int wid  = tid >> 5;
    const int g    = lane >> 2;
    const int t4   = lane & 3;
    const int wm   = wid >> 2;
    const int wn   = wid & 3;

    const int m0 = blockIdx.y * 128;
    const int K  = HID;

    float acc[16][4];
#pragma unroll
    for (int i = 0; i < 16; i++)
#pragma unroll
        for (int j = 0; j < 4; j++) acc[i][j] = 0.f;

    auto issue = [&](int s, int it) {
#pragma unroll
        for (int rep = 0; rep < 8; rep++) {
            int j = rep*256 + tid;
            int arr = j >> 10;
            int i = j & 1023;
            int row = i >> 3, q = (i & 7)*4;
            const uint32_t* src = (arr ? (B + (size_t)(n0 + row)*K)
                                       : (A + (size_t)(m0 + row)*K))
                                  + it*32 + q;
            uint32_t* dstb = (arr ? Bsm : Asm) + s*128*GST2 + row*GST2 + q;
            cpa16((uint32_t)__cvta_generic_to_shared(dstb), src);
        }
        asm volatile("cp.async.commit_group;" ::: "memory");
    };

    issue(0, 0);

    for (int it = 0; it < NK2; it++) {
        const int cur = it & 1;
        if (it + 1 < NK2) {
            issue(cur ^ 1, it + 1);
            asm volatile("cp.async.wait_group 1;" ::: "memory");
        } else {
            asm volatile("cp.async.wait_group 0;" ::: "memory");
        }
        __syncthreads();

        const uint32_t* Asc = Asm + cur*128*GST2;
        const uint32_t* Bsc = Bsm + cur*128*GST2;

#pragma unroll
        for (int kg2 = 0; kg2 < 2; kg2++) {
            const int off = kg2*16;
            uint2 tah[4][2], tal[4][2];
#pragma unroll
            for (int mt = 0; mt < 4; mt++) {
                const uint32_t* ar = Asc + (wm*64 + mt*16 + g)*GST2 + off;
                tah[mt][0] = *(const uint2*)(ar + 2*t4);
                tah[mt][1] = *(const uint2*)(ar + 8*GST2 + 2*t4);
                tal[mt][0] = *(const uint2*)(ar + 8 + 2*t4);
                tal[mt][1] = *(const uint2*)(ar + 8*GST2 + 8 + 2*t4);
            }
#pragma unroll
            for (int nt = 0; nt < 4; nt++) {
                const uint32_t* br = Bsc + (wn*32 + nt*8 + g)*GST2 + off;
                uint2 bh = *(const uint2*)(br + 2*t4);
                uint2 bl = *(const uint2*)(br + 8 + 2*t4);
#pragma unroll
                for (int mt = 0; mt < 4; mt++) {
                    float* c = acc[mt*4 + nt];
                    mma_bf16(c, tah[mt][0].x, tah[mt][1].x, tah[mt][0].y, tah[mt][1].y, bh.x, bh.y);
                    mma_bf16(c, tah[mt][0].x, tah[mt][1].x, tah[mt][0].y, tah[mt][1].y, bl.x, bl.y);
                    mma_bf16(c, tal[mt][0].x, tal[mt][1].x, tal[mt][0].y, tal[mt][1].y, bh.x, bh.y);
                }
            }
        }
        __syncthreads();
    }

    // ---- plain fp32 epilogue (O-proj all sets; fused V) ----
    if (!fuse || set == 2) {
#pragma unroll
        for (int mt = 0; mt < 4; mt++) {
#pragma unroll
            for (int nt = 0; nt < 4; nt++) {
                const float* c = acc[mt*4 + nt];
                int row0 = m0 + wm*64 + mt*16 + g;
                int col  = n0 + wn*32 + nt*8 + 2*t4;
                float b0 = bias ? bias[col]     : 0.f;
                float b1 = bias ? bias[col + 1] : 0.f;
                float2 v0 = make_float2(c[0] + b0, c[1] + b1);
                float2 v1 = make_float2(c[2] + b0, c[3] + b1);
                *(float2*)(C + (size_t)row0 * N + col)       = v0;
                *(float2*)(C + (size_t)(row0 + 8) * N + col) = v1;
            }
        }
    }

    if (fuse) {
        // stage acc+bias in smem exchange tile CT[128][CTS]
        float* CT = (float*)dyn;
#pragma unroll
        for (int mt = 0; mt < 4; mt++) {
#pragma unroll
            for (int nt = 0; nt < 4; nt++) {
                const float* c = acc[mt*4 + nt];
                int rl = wm*64 + mt*16 + g;
                int cl = wn*32 + nt*8 + 2*t4;
                float b0 = bias ? bias[n0 + cl]     : 0.f;
                float b1 = bias ? bias[n0 + cl + 1] : 0.f;
                *(float2*)(CT + (size_t)rl*CTS + cl)       = make_float2(c[0] + b0, c[1] + b1);
                *(float2*)(CT + (size_t)(rl + 8)*CTS + cl) = make_float2(c[2] + b0, c[3] + b1);
            }
        }
        __syncthreads();

        if (set <= 1) {
            // ---- RoPE + split -> packed Qs/Ks (+ roped fp32 K) ----
            const int rowwidth = (set == 0) ? HID : KVDIM;
            uint32_t* dstbase  = (set == 0) ? Qs : Ks;
            const int r = tid >> 1;
            const int t = m0 + r;
            const int s = t & (SEQ - 1);
            const float* ctr = CT + (size_t)r*CTS;
            uint32_t* drow = dstbase + (size_t)t*rowwidth + n0;
            float* kf = (set == 1) ? (C + (size_t)t*KVDIM + n0) : nullptr;
            const int jbase = (tid & 1)*32;
#pragma unroll 4
            for (int jj = 0; jj < 32; jj++) {
                int j = jbase + jj, f0 = 2*j;
                float c0 = cosb[s*HD + f0], c1 = cosb[s*HD + f0 + 1];
                float s0 = sinb[s*HD + f0], s1v = sinb[s*HD + f0 + 1];
                float xa = ctr[f0], xb = ctr[f0 + 1];
                int pf = (j < 32) ? f0 + 64 : f0 - 64;
                float pa = ctr[pf], pb = ctr[pf + 1];
                float rr0 = (j < 32) ? -pa : pa;
                float rr1 = (j < 32) ? -pb : pb;
                float o0 = xa*c0 + rr0*s0;
                float o1 = xb*c1 + rr1*s1v;
                uint32_t h, l;
                split_bf16(o0, o1, h, l);
                int w = (j >> 3)*16 + (j & 7);
                drow[w]     = h;
                drow[w + 8] = l;
                if (kf) { kf[f0] = o0; kf[f0 + 1] = o1; }
            }
        } else {
            // ---- V transpose + split -> Vt (word layout matches attention) ----
            const int kvh = n0 >> 7;
            const int b   = m0 >> 10;
            const int m0l = m0 & (SEQ - 1);
            uint32_t* outv = Vt + ((size_t)(b*NKV + kvh))*HD*SEQ + m0l;
            const int l = tid & 31;
            const int sh = l & 7;
            const int p  = (sh & 1) ? 4 + (sh >> 1) : (sh >> 1);
#pragma unroll 2
            for (int pass = 0; pass < 16; pass++) {
                int d = pass*8 + (tid >> 5);
#pragma unroll
                for (int lh = 0; lh < 2; lh++) {
                    int gi = lh*4 + (l >> 3);
                    int lt = gi*16 + 2*p;
                    uint32_t h, lo;
                    split_bf16(CT[(size_t)lt*CTS + d], CT[(size_t)(lt+1)*CTS + d], h, lo);
                    outv[(size_t)d*SEQ + gi*16 + sh]     = h;
                    outv[(size_t)d*SEQ + gi*16 + sh + 8] = lo;
                }
            }
        }
    }
}

// ---------------------------------------------------------------------------
// Scatter K/V into output kv buffer (unchanged)
// ---------------------------------------------------------------------------
__global__ void scatter_kernel(const float* __restrict__ K,
                               const float* __restrict__ V,
                               const void* __restrict__ idx,
                               float* __restrict__ buf)
{
    int t = blockIdx.x;
    int d = threadIdx.x;
    const long long* i64 = (const long long*)idx;
    const int*       i32 = (const int*)idx;
    bool is64 = ((unsigned long long)i64[1]) < (unsigned long long)(2*TOK);
    long long row = is64 ? i64[t] : (long long)i32[t];
    if (row < 0 || row >= (long long)(2*TOK)) return;
    size_t base = (size_t)row * 4 * HD;
    buf[base + 0*HD + d] = K[(size_t)t*KVDIM + d];
    buf[base + 1*HD + d] = K[(size_t)t*KVDIM + HD + d];
    buf[base + 2*HD + d] = V[(size_t)t*KVDIM + d];
    buf[base + 3*HD + d] = V[(size_t)t*KVDIM + HD + d];
}

// ---------------------------------------------------------------------------
// Tensor-core flash attention (R16, unchanged): P in registers,
// K/V double-buffered cp.async ping-pong, heavy q-tiles first,
// epilogue writes pre-split output for O-proj.
// ---------------------------------------------------------------------------
#define ABM 128
#define ABN 64
#define SQ2 136
#define SK2 136
#define SV2 72
#define STAGE_U32 (ABN*SK2 + ABM*SV2)
#define ATTN_SMEM ((ABM*SQ2 + 2*STAGE_U32) * sizeof(uint32_t))

__global__ __launch_bounds__(256, 1) void attn_ps_kernel(
    const uint32_t* __restrict__ Qs, const uint32_t* __restrict__ Ks,
    const uint32_t* __restrict__ Vt, uint32_t* __restrict__ As_out)
{
    extern __shared__ __align__(16) uint32_t smu[];
    uint32_t* sq = smu;

    const int bh  = blockIdx.y;
    const int b   = bh / NHEAD;
    const int h   = bh % NHEAD;
    const int kvh = h / (NHEAD / NKV);
    const int qt  = gridDim.x - 1 - blockIdx.x;
    const int tid = threadIdx.x;
    const int lane = tid & 31;
    const int wid  = tid >> 5;
    const int g    = lane >> 2;
    const int t4   = lane & 3;
    const float scale = 0.08838834764831845f;

    const int nkt = 2*qt + 2;
    const uint32_t* Vg = Vt + (size_t)(b*NKV + kvh)*HD*SEQ;
    const uint32_t* Kg = Ks + (size_t)(b*SEQ)*KVDIM + kvh*HD;

    auto issue = [&](int s, int kt) {
        uint32_t* sk = smu + ABM*SQ2 + s*STAGE_U32;
        uint32_t* sv = sk + ABN*SK2;
        for (int i = tid; i < ABN*32; i += 256) {
            int r = i >> 5, c4 = i & 31;
            cpa16((uint32_t)__cvta_generic_to_shared(sk + r*SK2 + c4*4),
                  Kg + (size_t)(kt*ABN + r)*KVDIM + c4*4);
        }
        for (int i = tid; i < ABM*16; i += 256) {
            int r = i >> 4, c4 = i & 15;
            cpa16((uint32_t)__cvta_generic_to_shared(sv + r*SV2 + c4*4),
                  Vg + (size_t)r*SEQ + kt*ABN + c4*4);
        }
        asm volatile("cp.async.commit_group;" ::: "memory");
    };

    issue(0, 0);

    const uint32_t* Qg = Qs + (size_t)(b*SEQ + qt*ABM)*HID + h*HD;
    for (int i = tid; i < ABM*32; i += 256) {
        int r = i >> 5, c4 = i & 31;
        *(uint4*)(sq + r*SQ2 + c4*4) = *(const uint4*)(Qg + (size_t)r*HID + c4*4);
    }

    float o[16][4];
#pragma unroll
    for (int i = 0; i < 16; i++)
#pragma unroll
        for (int j = 0; j < 4; j++) o[i][j] = 0.f;
    float mrow[2] = {-1e30f, -1e30f};
    float lrow[2] = {0.f, 0.f};

    const int qrow_base = qt*ABM + wid*16;

    for (int kt = 0; kt < nkt; kt++) {
        const int cur = kt & 1;
        if (kt + 1 < nkt) {
            issue(cur ^ 1, kt + 1);
            asm volatile("cp.async.wait_group 1;" ::: "memory");
        } else {
            asm volatile("cp.async.wait_group 0;" ::: "memory");
        }
        __syncthreads();

        const uint32_t* sk = smu + ABM*SQ2 + cur*STAGE_U32;
        const uint32_t* sv = sk + ABN*SK2;
        const int kcol_base = kt*ABN;
        const bool active = kcol_base <= qrow_base + 15;

        if (active) {
            float sacc[8][4];
#pragma unroll
            for (int i = 0; i < 8; i++)
#pragma unroll
                for (int j = 0; j < 4; j++) sacc[i][j] = 0.f;

#pragma unroll
            for (int kk = 0; kk < HD/16; kk++) {
                const uint32_t* qr = sq + (wid*16 + g)*SQ2 + kk*16 + 2*t4;
                uint2 ah02 = *(const uint2*)(qr);
                uint2 ah13 = *(const uint2*)(qr + 8*SQ2);
                uint2 al02 = *(const uint2*)(qr + 8);
                uint2 al13 = *(const uint2*)(qr + 8*SQ2 + 8);
#pragma unroll
                for (int nt = 0; nt < 8; nt++) {
                    const uint32_t* kr = sk + (nt*8 + g)*SK2 + kk*16 + 2*t4;
                    uint2 bhv = *(const uint2*)(kr);
                    uint2 blv = *(const uint2*)(kr + 8);
                    float* c = sacc[nt];
                    mma_bf16(c, ah02.x, ah13.x, ah02.y, ah13.y, bhv.x, bhv.y);
                    mma_bf16(c, ah02.x, ah13.x, ah02.y, ah13.y, blv.x, blv.y);
                    mma_bf16(c, al02.x, al13.x, al02.y, al13.y, bhv.x, bhv.y);
                }
            }

            const bool need_mask = (kcol_base + ABN - 1) > qrow_base;
            uint32_t ph[8][2], pl[8][2];
            float alpha2[2];
#pragma unroll
            for (int hh = 0; hh < 2; hh++) {
                const int qg = qrow_base + g + 8*hh;
                float mx = -1e30f;
#pragma unroll
                for (int nt = 0; nt < 8; nt++) {
#pragma unroll
                    for (int j = 0; j < 2; j++) {
                        float s = sacc[nt][2*hh + j] * scale;
                        if (need_mask) {
                            int kg2 = kcol_base + nt*8 + 2*t4 + j;
                            if (kg2 > qg) s = -1e30f;
                        }
                        sacc[nt][2*hh + j] = s;
                        mx = fmaxf(mx, s);
                    }
                }
                mx = fmaxf(mx, __shfl_xor_sync(0xffffffffu, mx, 1));
                mx = fmaxf(mx, __shfl_xor_sync(0xffffffffu, mx, 2));
                float mnew = fmaxf(mrow[hh], mx);
                float alpha = __expf(mrow[hh] - mnew);
                float sum = 0.f;
#pragma unroll
                for (int nt = 0; nt < 8; nt++) {
                    float p0 = __expf(sacc[nt][2*hh]     - mnew);
                    float p1 = __expf(sacc[nt][2*hh + 1] - mnew);
                    split_bf16(p0, p1, ph[nt][hh], pl[nt][hh]);
                    sum += p0 + p1;
                }
                sum += __shfl_xor_sync(0xffffffffu, sum, 1);
                sum += __shfl_xor_sync(0xffffffffu, sum, 2);
                lrow[hh] = lrow[hh]*alpha + sum;
                mrow[hh] = mnew;
                alpha2[hh] = alpha;
            }

#pragma unroll
            for (int nt = 0; nt < 16; nt++) {
                o[nt][0] *= alpha2[0]; o[nt][1] *= alpha2[0];
                o[nt][2] *= alpha2[1]; o[nt][3] *= alpha2[1];
            }

#pragma unroll
            for (int kk = 0; kk < ABN/16; kk++) {
                const uint32_t a0h = ph[2*kk][0],   a1h = ph[2*kk][1];
                const uint32_t a2h = ph[2*kk+1][0], a3h = ph[2*kk+1][1];
                const uint32_t a0l = pl[2*kk][0],   a1l = pl[2*kk][1];
                const uint32_t a2l = pl[2*kk+1][0], a3l = pl[2*kk+1][1];
#pragma unroll
                for (int nt = 0; nt < 16; nt++) {
                    const uint32_t* vr = sv + (nt*8 + g)*SV2 + kk*16 + 2*t4;
                    uint2 bhv = *(const uint2*)(vr);
                    uint2 blv = *(const uint2*)(vr + 8);
                    float* c = o[nt];
                    mma_bf16(c, a0h, a1h, a2h, a3h, bhv.x, bhv.y);
                    mma_bf16(c, a0h, a1h, a2h, a3h, blv.x, blv.y);
                    mma_bf16(c, a0l, a1l, a2l, a3l, bhv.x, bhv.y);
                }
            }
        }
        __syncthreads();
    }

    const float inv0 = 1.f / lrow[0];
    const float inv1 = 1.f / lrow[1];
    const int r0 = qt*ABM + wid*16 + g;
    const size_t grow0 = (size_t)(b*SEQ + r0) * HID;
    const size_t grow1 = grow0 + 8*(size_t)HID;
#pragma unroll
    for (int nt = 0; nt < 16; nt++) {
        int colg = h*HD + nt*8 + 2*t4;
        int kg = colg >> 4;
        int p  = (colg >> 1) & 7;
        size_t i0 = grow0 + kg*16 + p;
        size_t i1 = grow1 + kg*16 + p;
        uint32_t h0, l0, h1, l1;
        split_bf16(o[nt][0]*inv0, o[nt][1]*inv0, h0, l0);
        split_bf16(o[nt][2]*inv1, o[nt][3]*inv1, h1, l1);
        As_out[i0]     = h0;
        As_out[i0 + 8] = l0;
        As_out[i1]     = h1;
        As_out[i1 + 8] = l1;
    }
}

// ---------------------------------------------------------------------------
// Launch.
// ---------------------------------------------------------------------------
extern "C" void kernel_launch(void* const* d_in, const int* in_sizes, int n_in,
                              void* d_out, int out_size)
{
    const void* slot[12];
    if (n_in >= 12 && in_sizes[0] == (int)(TOK*(size_t)HID)) {
        for (int i = 0; i < 12; i++) slot[i] = d_in[i];
    } else {
        // alphabetical: cos,k_b,k_w,kv_buffer,o_w,q_b,q_w,select_index,sin,v_b,v_w,x
        slot[8]  = d_in[0];
        slot[4]  = d_in[1];
        slot[3]  = d_in[2];
        slot[10] = d_in[3];
        slot[7]  = d_in[4];
        slot[2]  = d_in[5];
        slot[1]  = d_in[6];
        slot[11] = d_in[7];
        slot[9]  = d_in[8];
        slot[6]  = d_in[9];
        slot[5]  = d_in[10];
        slot[0]  = d_in[11];
    }

    const float* x     = (const float*)slot[0];
    const float* q_w   = (const float*)slot[1];
    const float* q_b   = (const float*)slot[2];
    const float* k_w   = (const float*)slot[3];
    const float* k_b   = (const float*)slot[4];
    const float* v_w   = (const float*)slot[5];
    const float* v_b   = (const float*)slot[6];
    const float* o_w   = (const float*)slot[7];
    const float* cosb  = (const float*)slot[8];
    const float* sinb  = (const float*)slot[9];
    const float* kvbuf = (const float*)slot[10];
    const void*  sel   = slot[11];

    float* out = (float*)d_out;
    bool has_buf = (size_t)out_size >= OUT_ELEMS + BUF_ELEMS;
    float* buf_out = out + ((size_t)out_size - BUF_ELEMS);

    float *K, *V;
    uint32_t *xs, *qws, *kws, *vws, *ows, *As, *Qsp, *Ksp, *Vtp;
    cudaGetSymbolAddress((void**)&K, g_K);
    cudaGetSymbolAddress((void**)&V, g_V);
    cudaGetSymbolAddress((void**)&xs, g_xs);
    cudaGetSymbolAddress((void**)&qws, g_qws);
    cudaGetSymbolAddress((void**)&kws, g_kws);
    cudaGetSymbolAddress((void**)&vws, g_vws);
    cudaGetSymbolAddress((void**)&ows, g_ows);
    cudaGetSymbolAddress((void**)&As, g_As);
    cudaGetSymbolAddress((void**)&Qsp, g_Qs);
    cudaGetSymbolAddress((void**)&Ksp, g_Ks);
    cudaGetSymbolAddress((void**)&Vtp, g_Vt);

    // Pre-split inputs
    presplit_kernel<<<(TOK*HID/8 + 255)/256, 256>>>(x, xs, TOK*HID/8);
    presplit_kernel<<<(HID*HID/8 + 255)/256, 256>>>(q_w, qws, HID*HID/8);
    presplit_kernel<<<(KVDIM*HID/8 + 255)/256, 256>>>(k_w, kws, KVDIM*HID/8);
    presplit_kernel<<<(KVDIM*HID/8 + 255)/256, 256>>>(v_w, vws, KVDIM*HID/8);
    presplit_kernel<<<(HID*HID/8 + 255)/256, 256>>>(o_w, ows, HID*HID/8);

    cudaFuncSetAttribute(gemm_big_kernel,
                         cudaFuncAttributeMaxDynamicSharedMemorySize, GEMM_SMEM);

    // Fused QKV projections + rope/split + V transpose/split:
    // bx 0-15 Q -> Qs; 16-17 K -> Ks + fp32 K; 18-19 V -> fp32 V + Vt
    gemm_big_kernel<<<dim3(20, TOK/128, 1), 256, GEMM_SMEM>>>(
        xs,
        qws, q_b, nullptr, HID,
        kws, k_b, K, KVDIM,
        vws, v_b, V, KVDIM,
        16, 18, 1, cosb, sinb, Qsp, Ksp, Vtp);

    // KV buffer output (roped fp32 K, fp32 V)
    if (has_buf) {
        cudaMemcpyAsync(buf_out, kvbuf, BUF_ELEMS * sizeof(float),
                        cudaMemcpyDeviceToDevice);
        scatter_kernel<<<TOK, 128>>>(K, V, sel, buf_out);
    }

    // Attention
    cudaFuncSetAttribute(attn_ps_kernel,
                         cudaFuncAttributeMaxDynamicSharedMemorySize,
                         (int)ATTN_SMEM);
    attn_ps_kernel<<<dim3(SEQ/ABM, BATCH*NHEAD), 256, ATTN_SMEM>>>(Qsp, Ksp, Vtp, As);

    // O projection (plain epilogue)
    gemm_big_kernel<<<dim3(16, TOK/128, 1), 256, GEMM_SMEM>>>(
        As,
        ows, nullptr, out, HID,
        ows, nullptr, out, HID,
        ows, nullptr, out, HID,
        16, 17, 0, nullptr, nullptr, nullptr, nullptr, nullptr);
}